// round 17
// baseline (speedup 1.0000x reference)
#include <cuda_runtime.h>
#include <math.h>

#define NVERT 289
#define NFACE 512
#define IMGS  128
#define KF    8
#define MAXC  64
#define NTH   256

#define KEY_INVALID 0xFFFFFFFFu

// ---------------------------------------------------------------------------
// Face connectivity: replicate _build_faces(17,17) analytically.
// ---------------------------------------------------------------------------
__device__ __forceinline__ void face_vids(int f, int& i0, int& i1, int& i2) {
    int grp = f >> 6;
    int g   = f & 63;
    int nyi = g >> 3;
    int nxi = g & 7;
    int ny = (grp >= 4) ? (1 + 2 * nyi) : (2 * nyi);
    int nx;
    if (grp == 0 || grp == 1 || grp == 6 || grp == 7) nx = 1 + 2 * nxi;
    else                                              nx = 2 * nxi;
    int a  = ny * 17 + nx;
    int r  = a + 1;
    int d  = a + 17;
    int dr = a + 18;
    switch (grp) {
        case 0: i0 = r;  i1 = a; i2 = d;  break;
        case 1: i0 = r;  i1 = d; i2 = dr; break;
        case 2: i0 = r;  i1 = a; i2 = dr; break;
        case 3: i0 = dr; i1 = a; i2 = d;  break;
        case 4: i0 = r;  i1 = a; i2 = d;  break;
        case 5: i0 = r;  i1 = d; i2 = dr; break;
        case 6: i0 = r;  i1 = a; i2 = dr; break;
        default:i0 = dr; i1 = a; i2 = d;  break;
    }
}

__device__ __forceinline__ float seg_d2_fast(float px, float py,
                                             float sx, float sy,
                                             float ex, float ey, float invL) {
    float dx = ex - sx, dy = ey - sy;
    float t = ((px - sx) * dx + (py - sy) * dy) * invL;
    t = fminf(fmaxf(t, 0.0f), 1.0f);
    float ux = px - (sx + t * dx);
    float uy = py - (sy + t * dy);
    return ux * ux + uy * uy;
}

// Single-divide clamped-bary eval. Identity: with m_i = max(sign(den)*n_i, 0),
// bary_i = m_i/Sum(m) and zpix = Sum(m_i z_i)/Sum(m) — den cancels exactly
// (reference's Sum-c >= 1e-10 clamp never binds: Sum(m) >= |den|).
// P0/P1/P2 = (K, X, Y, invL): b = K + px*X + py*Y (scaled by 1/area_s)
// G0 = (ax, ay, bx, by); G1 = (cx, cy, z0, z1); G2 = (z2, z1z2, z0z2, z0z1)
__device__ __forceinline__ bool eval_sel(float px, float py,
                                         float4 P0, float4 P1, float4 P2,
                                         float4 G0, float4 G1, float4 G2,
                                         float& zpix) {
    float b0 = fmaf(py, P0.z, fmaf(px, P0.y, P0.x));
    float b1 = fmaf(py, P1.z, fmaf(px, P1.y, P1.x));
    float b2 = fmaf(py, P2.z, fmaf(px, P2.y, P2.x));
    bool inside = (b0 >= 0.0f) && (b1 >= 0.0f) && (b2 >= 0.0f);
    float n0 = b0 * G2.y, n1 = b1 * G2.z, n2 = b2 * G2.w;
    float den = n0 + n1 + n2;
    den = (fabsf(den) < 1e-10f) ? 1e-10f : den;
    float sgn = (den < 0.0f) ? -1.0f : 1.0f;
    float m0 = fmaxf(n0 * sgn, 0.0f);
    float m1 = fmaxf(n1 * sgn, 0.0f);
    float m2 = fmaxf(n2 * sgn, 0.0f);
    float sum = fmaxf(m0 + m1 + m2, 1e-20f);
    zpix = __fdividef(fmaf(m2, G2.x, fmaf(m1, G1.w, m0 * G1.z)), sum);
    float d2 = fminf(fminf(seg_d2_fast(px, py, G0.x, G0.y, G0.z, G0.w, P0.w),
                           seg_d2_fast(px, py, G0.z, G0.w, G1.x, G1.y, P1.w)),
                     seg_d2_fast(px, py, G1.x, G1.y, G0.x, G0.y, P2.w));
    float sdist = inside ? -d2 : d2;
    return (sdist < 1e-4f) && (zpix > 1e-4f);
}

// Full eval for shading (same identity; one reciprocal for bn).
__device__ __forceinline__ void eval_full(float px, float py,
                                          float4 P0, float4 P1, float4 P2,
                                          float4 G0, float4 G1, float4 G2,
                                          float& sdist, float& zpix,
                                          float& bn0, float& bn1, float& bn2) {
    float b0 = fmaf(py, P0.z, fmaf(px, P0.y, P0.x));
    float b1 = fmaf(py, P1.z, fmaf(px, P1.y, P1.x));
    float b2 = fmaf(py, P2.z, fmaf(px, P2.y, P2.x));
    bool inside = (b0 >= 0.0f) && (b1 >= 0.0f) && (b2 >= 0.0f);
    float n0 = b0 * G2.y, n1 = b1 * G2.z, n2 = b2 * G2.w;
    float den = n0 + n1 + n2;
    den = (fabsf(den) < 1e-10f) ? 1e-10f : den;
    float sgn = (den < 0.0f) ? -1.0f : 1.0f;
    float m0 = fmaxf(n0 * sgn, 0.0f);
    float m1 = fmaxf(n1 * sgn, 0.0f);
    float m2 = fmaxf(n2 * sgn, 0.0f);
    float sum = fmaxf(m0 + m1 + m2, 1e-20f);
    float rsum = __fdividef(1.0f, sum);
    bn0 = m0 * rsum; bn1 = m1 * rsum; bn2 = m2 * rsum;
    zpix = fmaf(m2, G2.x, fmaf(m1, G1.w, m0 * G1.z)) * rsum;
    float d2 = fminf(fminf(seg_d2_fast(px, py, G0.x, G0.y, G0.z, G0.w, P0.w),
                           seg_d2_fast(px, py, G0.z, G0.w, G1.x, G1.y, P1.w)),
                     seg_d2_fast(px, py, G1.x, G1.y, G0.x, G0.y, P2.w));
    sdist = inside ? -d2 : d2;
}

__global__ void __launch_bounds__(NTH)
nvp_kernel(const float* __restrict__ xy_off,
           const float* __restrict__ z_grid,
           const float* __restrict__ tex,
           const float* __restrict__ R_in,
           const float* __restrict__ T_in,
           const float* __restrict__ R_out,
           const float* __restrict__ T_out,
           float* __restrict__ out) {
    __shared__ float  s_vx[NVERT], s_vy[NVERT], s_vz[NVERT];
    __shared__ float4 s_P0[MAXC], s_P1[MAXC], s_P2[MAXC];
    __shared__ float4 s_G0[MAXC], s_G1[MAXC], s_G2[MAXC];
    __shared__ float4 s_U[MAXC], s_V[MAXC];
    __shared__ int    s_wc[8];

    const int tid  = threadIdx.x;
    const int lane = tid & 31;
    const int wid  = tid >> 5;
    const int sub  = tid & 3;
    const int pixb = tid >> 2;
    const int tx   = blockIdx.x & 15;
    const int ty   = blockIdx.x >> 4;
    const int ix   = tx * 8 + (pixb & 7);
    const int iy   = ty * 8 + (pixb >> 3);
    const float px = 1.0f - (float)(2 * ix + 1) * 0.0078125f;
    const float py = 1.0f - (float)(2 * iy + 1) * 0.0078125f;
    const float pxhi = 1.0f - (float)(2 * (tx * 8) + 1) * 0.0078125f;
    const float pxlo = 1.0f - (float)(2 * (tx * 8 + 7) + 1) * 0.0078125f;
    const float pyhi = 1.0f - (float)(2 * (ty * 8) + 1) * 0.0078125f;
    const float pylo = 1.0f - (float)(2 * (ty * 8 + 7) + 1) * 0.0078125f;

    // --- vertex transform (vectorized uniform loads) ---
    {
        const float4* R4i = (const float4*)R_in;
        const float4* R4o = (const float4*)R_out;
        float4 ri0 = __ldg(R4i), ri1 = __ldg(R4i + 1);
        float  ri8 = __ldg(R_in + 8);
        float4 ro0 = __ldg(R4o), ro1 = __ldg(R4o + 1);
        float  ro8 = __ldg(R_out + 8);
        float2 ti01 = __ldg((const float2*)T_in);
        float  ti2  = __ldg(T_in + 2);
        float2 to01 = __ldg((const float2*)T_out);
        float  to2  = __ldg(T_out + 2);
        const float SCALE = 0.57735026918962576451f;   // tan(30deg)
        const float SINV  = 1.7320508075688772935f;    // 1/SCALE
        for (int v = tid; v < NVERT; v += NTH) {
            float xs = -1.0f + (float)(v % 17) * 0.125f;
            float ys = -1.0f + (float)(v / 17) * 0.125f;
            float2 xo = __ldg((const float2*)(xy_off) + v);
            float gx = (xs + xo.x) * SCALE;
            float gy = (ys + xo.y) * SCALE;
            float zg = __ldg(z_grid + v);
            float sx = gx * zg, sy = gy * zg, sz = zg;
            float p0 = sx - ti01.x, p1 = sy - ti01.y, p2 = sz - ti2;
            float w0 = ri0.x * p0 + ri0.y * p1 + ri0.z * p2;
            float w1 = ri0.w * p0 + ri1.x * p1 + ri1.y * p2;
            float w2 = ri1.z * p0 + ri1.w * p1 + ri8  * p2;
            float vx = ro0.x * w0 + ro0.w * w1 + ro1.z * w2 + to01.x;
            float vy = ro0.y * w0 + ro1.x * w1 + ro1.w * w2 + to01.y;
            float vz = ro0.z * w0 + ro1.y * w1 + ro8  * w2 + to2;
            float zden = (vz >= 0.0f) ? fmaxf(vz, 0.01f) : fminf(vz, -0.01f);
            float rz = __fdividef(1.0f, zden);
            s_vx[v] = SINV * vx * rz;
            s_vy[v] = SINV * vy * rz;
            s_vz[v] = vz;
        }
    }
    __syncthreads();

    // --- face setup + single-sync order-preserving pair compaction ---
    const float M = 0.0105f;   // blur reach sqrt(1e-4)=0.01 + fp margin
    int total = 0;
    {
        const int f0 = 2 * tid, f1 = f0 + 1;
        int a0, a1, a2, b0i, b1i, b2i;
        face_vids(f0, a0, a1, a2);
        face_vids(f1, b0i, b1i, b2i);
        float ax0 = s_vx[a0], ay0 = s_vy[a0], az0 = s_vz[a0];
        float bx0 = s_vx[a1], by0 = s_vy[a1], bz0 = s_vz[a1];
        float cx0 = s_vx[a2], cy0 = s_vy[a2], cz0 = s_vz[a2];
        float ax1 = s_vx[b0i], ay1 = s_vy[b0i], az1 = s_vz[b0i];
        float bx1 = s_vx[b1i], by1 = s_vy[b1i], bz1 = s_vz[b1i];
        float cx1 = s_vx[b2i], cy1 = s_vy[b2i], cz1 = s_vz[b2i];

        float xm0 = fminf(ax0, fminf(bx0, cx0)) - M;
        float xM0 = fmaxf(ax0, fmaxf(bx0, cx0)) + M;
        float ym0 = fminf(ay0, fminf(by0, cy0)) - M;
        float yM0 = fmaxf(ay0, fmaxf(by0, cy0)) + M;
        float xm1 = fminf(ax1, fminf(bx1, cx1)) - M;
        float xM1 = fmaxf(ax1, fmaxf(bx1, cx1)) + M;
        float ym1 = fminf(ay1, fminf(by1, cy1)) - M;
        float yM1 = fmaxf(ay1, fmaxf(by1, cy1)) + M;
        bool e0 = (xm0 <= pxhi) && (xM0 >= pxlo) && (ym0 <= pyhi) && (yM0 >= pylo);
        bool e1 = (xm1 <= pxhi) && (xM1 >= pxlo) && (ym1 <= pyhi) && (yM1 >= pylo);

        unsigned em = __ballot_sync(0xffffffffu, e0);
        unsigned om = __ballot_sync(0xffffffffu, e1);
        if (lane == 0) s_wc[wid] = __popc(em) + __popc(om);
        __syncthreads();
        unsigned below = (1u << lane) - 1u;
        int posw = __popc(em & below) + __popc(om & below);
        int base = 0;
#pragma unroll
        for (int w = 0; w < 8; w++) {
            if (w < wid) base += s_wc[w];
            total += s_wc[w];
        }
        int p0 = base + posw;
        int p1 = p0 + (e0 ? 1 : 0);

        if (e0 && p0 < MAXC) {
            float area = (bx0 - ax0) * (cy0 - ay0) - (by0 - ay0) * (cx0 - ax0);
            float area_s = (fabsf(area) < 1e-8f) ? 1e-8f : area;
            float ia = __fdividef(1.0f, area_s);
            float Lab = fmaxf((bx0-ax0)*(bx0-ax0) + (by0-ay0)*(by0-ay0), 1e-12f);
            float Lbc = fmaxf((cx0-bx0)*(cx0-bx0) + (cy0-by0)*(cy0-by0), 1e-12f);
            float Lca = fmaxf((ax0-cx0)*(ax0-cx0) + (ay0-cy0)*(ay0-cy0), 1e-12f);
            s_P0[p0] = make_float4((bx0*cy0 - by0*cx0) * ia, (by0-cy0) * ia,
                                   (cx0-bx0) * ia, __fdividef(1.0f, Lab));
            s_P1[p0] = make_float4((cx0*ay0 - cy0*ax0) * ia, (cy0-ay0) * ia,
                                   (ax0-cx0) * ia, __fdividef(1.0f, Lbc));
            s_P2[p0] = make_float4((ax0*by0 - ay0*bx0) * ia, (ay0-by0) * ia,
                                   (bx0-ax0) * ia, __fdividef(1.0f, Lca));
            s_G0[p0] = make_float4(ax0, ay0, bx0, by0);
            s_G1[p0] = make_float4(cx0, cy0, az0, bz0);
            s_G2[p0] = make_float4(cz0, bz0 * cz0, az0 * cz0, az0 * bz0);
            s_U[p0]  = make_float4(1.0f - (float)(a0 % 17) * 0.0625f,
                                   1.0f - (float)(a1 % 17) * 0.0625f,
                                   1.0f - (float)(a2 % 17) * 0.0625f, 0.0f);
            s_V[p0]  = make_float4((float)(a0 / 17) * 0.0625f,
                                   (float)(a1 / 17) * 0.0625f,
                                   (float)(a2 / 17) * 0.0625f, 0.0f);
        }
        if (e1 && p1 < MAXC) {
            float area = (bx1 - ax1) * (cy1 - ay1) - (by1 - ay1) * (cx1 - ax1);
            float area_s = (fabsf(area) < 1e-8f) ? 1e-8f : area;
            float ia = __fdividef(1.0f, area_s);
            float Lab = fmaxf((bx1-ax1)*(bx1-ax1) + (by1-ay1)*(by1-ay1), 1e-12f);
            float Lbc = fmaxf((cx1-bx1)*(cx1-bx1) + (cy1-by1)*(cy1-by1), 1e-12f);
            float Lca = fmaxf((ax1-cx1)*(ax1-cx1) + (ay1-cy1)*(ay1-cy1), 1e-12f);
            s_P0[p1] = make_float4((bx1*cy1 - by1*cx1) * ia, (by1-cy1) * ia,
                                   (cx1-bx1) * ia, __fdividef(1.0f, Lab));
            s_P1[p1] = make_float4((cx1*ay1 - cy1*ax1) * ia, (cy1-ay1) * ia,
                                   (ax1-cx1) * ia, __fdividef(1.0f, Lbc));
            s_P2[p1] = make_float4((ax1*by1 - ay1*bx1) * ia, (ay1-by1) * ia,
                                   (bx1-ax1) * ia, __fdividef(1.0f, Lca));
            s_G0[p1] = make_float4(ax1, ay1, bx1, by1);
            s_G1[p1] = make_float4(cx1, cy1, az1, bz1);
            s_G2[p1] = make_float4(cz1, bz1 * cz1, az1 * cz1, az1 * bz1);
            s_U[p1]  = make_float4(1.0f - (float)(b0i % 17) * 0.0625f,
                                   1.0f - (float)(b1i % 17) * 0.0625f,
                                   1.0f - (float)(b2i % 17) * 0.0625f, 0.0f);
            s_V[p1]  = make_float4((float)(b0i / 17) * 0.0625f,
                                   (float)(b1i / 17) * 0.0625f,
                                   (float)(b2i / 17) * 0.0625f, 0.0f);
        }
        __syncthreads();
    }
    if (total > MAXC) total = MAXC;

    // --- selection: dual-face ILP per iteration (i and i+4), guarded insert ---
    unsigned kk[KF];
#pragma unroll
    for (int k = 0; k < KF; k++) kk[k] = KEY_INVALID;

    for (int i = sub; i < total; i += 8) {
        int j2 = i + 4;
        bool h2 = (j2 < total);
        int jc = h2 ? j2 : i;
        float4 Pa0 = s_P0[i],  Pa1 = s_P1[i],  Pa2 = s_P2[i];
        float4 Ga0 = s_G0[i],  Ga1 = s_G1[i],  Ga2 = s_G2[i];
        float4 Pb0 = s_P0[jc], Pb1 = s_P1[jc], Pb2 = s_P2[jc];
        float4 Gb0 = s_G0[jc], Gb1 = s_G1[jc], Gb2 = s_G2[jc];
        float z1, z2;
        bool v1 = eval_sel(px, py, Pa0, Pa1, Pa2, Ga0, Ga1, Ga2, z1);
        bool v2 = eval_sel(px, py, Pb0, Pb1, Pb2, Gb0, Gb1, Gb2, z2) && h2;
        unsigned key1 = (__float_as_uint(z1) & 0xFFFFFFC0u) | (unsigned)i;
        if (v1 && key1 < kk[KF - 1]) {
#pragma unroll
            for (int j = 0; j < KF; j++) {
                if (key1 < kk[j]) { unsigned t = kk[j]; kk[j] = key1; key1 = t; }
            }
        }
        unsigned key2 = (__float_as_uint(z2) & 0xFFFFFFC0u) | (unsigned)j2;
        if (v2 && key2 < kk[KF - 1]) {
#pragma unroll
            for (int j = 0; j < KF; j++) {
                if (key2 < kk[j]) { unsigned t = kk[j]; kk[j] = key2; key2 = t; }
            }
        }
    }

    // --- merge 4 per-lane sorted lists (u32 keys) ---
    // Round 1 (xor 1): full merge + bitonic cleanup.
    {
        unsigned bk[KF];
#pragma unroll
        for (int i = 0; i < KF; i++)
            bk[i] = __shfl_xor_sync(0xffffffffu, kk[i], 1);
        unsigned ck[KF];
#pragma unroll
        for (int i = 0; i < KF; i++)
            ck[i] = min(kk[i], bk[KF - 1 - i]);
#pragma unroll
        for (int d2 = 4; d2 >= 1; d2 >>= 1) {
#pragma unroll
            for (int i = 0; i < KF; i++) {
                if ((i & d2) == 0) {
                    int j = i + d2;
                    unsigned lo = min(ck[i], ck[j]);
                    unsigned hi = max(ck[i], ck[j]);
                    ck[i] = lo; ck[j] = hi;
                }
            }
        }
#pragma unroll
        for (int i = 0; i < KF; i++) kk[i] = ck[i];
    }
    // Round 2 (xor 2): min-merge only; lanes 2,3 hold exact reverse(set).
    {
        unsigned bk[KF];
#pragma unroll
        for (int i = 0; i < KF; i++)
            bk[i] = __shfl_xor_sync(0xffffffffu, kk[i], 2);
#pragma unroll
        for (int i = 0; i < KF; i++)
            kk[i] = min(kk[i], bk[KF - 1 - i]);
    }

    // Reversal-aware assignment (R8-proven): lane0:{0,4} lane1:{1,5}
    // lane2:{5,1} lane3:{4,0} covers the 8-element set exactly once.
    unsigned ks[2];
    ks[0] = (sub == 0) ? kk[0] : (sub == 1) ? kk[1] : (sub == 2) ? kk[5] : kk[4];
    ks[1] = (sub == 0) ? kk[4] : (sub == 1) ? kk[5] : (sub == 2) ? kk[1] : kk[0];

    // --- shade: branch-free (invalid -> dummy face 0, results zeroed) ---
    const float R99 = 0.010101010101010102f;
    float pr[2], zin[2], zsv[2], cr[2], cg[2], cb[2];
#pragma unroll
    for (int t = 0; t < 2; t++) {
        bool live = (ks[t] != KEY_INVALID);
        int ci = live ? (int)(ks[t] & 63u) : 0;
        float4 P0 = s_P0[ci], P1 = s_P1[ci], P2 = s_P2[ci];
        float4 G0 = s_G0[ci], G1 = s_G1[ci], G2 = s_G2[ci];
        float sdist, zpix, bn0, bn1, bn2;
        eval_full(px, py, P0, P1, P2, G0, G1, G2, sdist, zpix, bn0, bn1, bn2);
        float4 U = s_U[ci], V = s_V[ci];
        float uu = bn0 * U.x + bn1 * U.y + bn2 * U.z;
        float vv = bn0 * V.x + bn1 * V.y + bn2 * V.z;
        float tx2 = uu * 127.0f;
        float ty2 = (1.0f - vv) * 127.0f;
        float x0f = fminf(fmaxf(floorf(tx2), 0.0f), 127.0f);
        float y0f = fminf(fmaxf(floorf(ty2), 0.0f), 127.0f);
        int x0 = (int)x0f, y0 = (int)y0f;
        int x1 = min(x0 + 1, 127), y1 = min(y0 + 1, 127);
        float wx = tx2 - x0f, wy = ty2 - y0f;
        const float* p00 = tex + (y0 * IMGS + x0) * 3;
        const float* p01 = tex + (y0 * IMGS + x1) * 3;
        const float* p10 = tex + (y1 * IMGS + x0) * 3;
        const float* p11 = tex + (y1 * IMGS + x1) * 3;
        float omwx = 1.0f - wx, omwy = 1.0f - wy;
        float tcr = omwy * (omwx * __ldg(p00 + 0) + wx * __ldg(p01 + 0)) +
                    wy   * (omwx * __ldg(p10 + 0) + wx * __ldg(p11 + 0));
        float tcg = omwy * (omwx * __ldg(p00 + 1) + wx * __ldg(p01 + 1)) +
                    wy   * (omwx * __ldg(p10 + 1) + wx * __ldg(p11 + 1));
        float tcb = omwy * (omwx * __ldg(p00 + 2) + wx * __ldg(p01 + 2)) +
                    wy   * (omwx * __ldg(p10 + 2) + wx * __ldg(p11 + 2));
        float tpr = __fdividef(1.0f, 1.0f + __expf(sdist * 1e4f));  // sigmoid(-d/SIGMA)
        pr[t]  = live ? tpr : 0.0f;
        zsv[t] = live ? zpix : 0.0f;
        zin[t] = live ? (100.0f - zpix) * R99 : 0.0f;
        cr[t]  = live ? tcr : 0.0f;
        cg[t]  = live ? tcg : 0.0f;
        cb[t]  = live ? tcb : 0.0f;
    }

    // --- zmax: quad set-max over recomputed zinv (covers all 8 selected) ---
    float zmax = fmaxf(1e-10f, fmaxf(zin[0], zin[1]));
#pragma unroll
    for (int d = 1; d <= 2; d <<= 1)
        zmax = fmaxf(zmax, __shfl_xor_sync(0xffffffffu, zmax, d));
    float delta = __expf((1e-10f - zmax) * 1e4f);

    // --- weights + accumulate (dead slots: pr=0 -> w=0) ---
    float sw = 0.0f, sr = 0.0f, sg = 0.0f, sb = 0.0f, sd = 0.0f, ap = 1.0f;
#pragma unroll
    for (int t = 0; t < 2; t++) {
        float w = pr[t] * __expf((zin[t] - zmax) * 1e4f);
        sw += w;
        sr += w * cr[t];
        sg += w * cg[t];
        sb += w * cb[t];
        sd += w * zsv[t];
        ap *= (1.0f - pr[t]);
    }

    // --- quad butterfly reduction ---
#pragma unroll
    for (int d = 1; d <= 2; d <<= 1) {
        sw += __shfl_xor_sync(0xffffffffu, sw, d);
        sr += __shfl_xor_sync(0xffffffffu, sr, d);
        sg += __shfl_xor_sync(0xffffffffu, sg, d);
        sb += __shfl_xor_sync(0xffffffffu, sb, d);
        sd += __shfl_xor_sync(0xffffffffu, sd, d);
        ap *= __shfl_xor_sync(0xffffffffu, ap, d);
    }
    float rdenom = __fdividef(1.0f, sw + delta);

    int o = (iy * IMGS + ix) * 5;
    if (sub == 0) {
        out[o + 0] = sr * rdenom;
        out[o + 4] = (sd + delta * 100.0f) * rdenom;
    } else if (sub == 1) {
        out[o + 1] = sg * rdenom;
    } else if (sub == 2) {
        out[o + 2] = sb * rdenom;
    } else {
        out[o + 3] = 1.0f - ap;
    }
}

extern "C" void kernel_launch(void* const* d_in, const int* in_sizes, int n_in,
                              void* d_out, int out_size) {
    (void)in_sizes; (void)n_in; (void)out_size;
    nvp_kernel<<<256, NTH>>>(
        (const float*)d_in[0],   // xy_offset (1,289,2)
        (const float*)d_in[1],   // z_grid    (1,289,1)
        (const float*)d_in[2],   // rgb_in    (1,128,128,3)
        (const float*)d_in[3],   // R_in      (1,3,3)
        (const float*)d_in[4],   // T_in      (1,3)
        (const float*)d_in[5],   // R_out     (1,3,3)
        (const float*)d_in[6],   // T_out     (1,3)
        (float*)d_out);          // (1,128,128,5) float32
}